// round 6
// baseline (speedup 1.0000x reference)
#include <cuda_runtime.h>
#include <cuda_bf16.h>

// Haar DWT, single level. Input (16,64,256,256) fp32 -> output (16,256,128,128).
// Persistent grid-stride version of the R1 shape: 1184 CTAs (148 SMs x occ 8),
// each thread loops over ~14 work items. Per item: 4 x LDG.128, 4 x STG.128.

static constexpr int B = 16;
static constexpr int C = 64;
static constexpr int H = 256;
static constexpr int W = 256;
static constexpr int H2 = H / 2;   // 128
static constexpr int W2 = W / 2;   // 128
static constexpr int W4 = W2 / 4;  // 32 work items per output row
static constexpr int TOTAL = B * C * H2 * W4;  // 4,194,304 work items

static constexpr int THREADS = 256;
static constexpr int BLOCKS = 148 * 8;  // 1184 persistent CTAs

__global__ __launch_bounds__(THREADS)
void dwt_haar_kernel(const float* __restrict__ x, float* __restrict__ out) {
    const unsigned stride = gridDim.x * blockDim.x;   // 303,104
    constexpr size_t plane_f4 = (size_t)(H2 * W2) / 4;

    for (unsigned idx = blockIdx.x * blockDim.x + threadIdx.x; idx < TOTAL; idx += stride) {
        // idx layout: [bc][h2][w4] — consecutive idx = consecutive memory
        unsigned w4 = idx & (W4 - 1);            // 0..31
        unsigned h2 = (idx >> 5) & (H2 - 1);     // 0..127
        unsigned bc = idx >> 12;                 // 0..B*C-1

        const float* plane = x + (size_t)bc * (H * W);
        unsigned col = w4 * 8;                   // first of 8 input columns
        const float4* r0 = reinterpret_cast<const float4*>(plane + (size_t)(2 * h2) * W + col);
        const float4* r1 = reinterpret_cast<const float4*>(plane + (size_t)(2 * h2 + 1) * W + col);

        float4 t0 = __ldg(r0 + 0);
        float4 t1 = __ldg(r0 + 1);
        float4 b0 = __ldg(r1 + 0);
        float4 b1 = __ldg(r1 + 1);

        float a0 = t0.x, e0 = t0.y, c0 = b0.x, d0 = b0.y;
        float a1 = t0.z, e1 = t0.w, c1 = b0.z, d1 = b0.w;
        float a2 = t1.x, e2 = t1.y, c2 = b1.x, d2 = b1.y;
        float a3 = t1.z, e3 = t1.w, c3 = b1.z, d3 = b1.w;

        float4 cA, cH, cV, cD;
        cA.x = (a0 + e0 + c0 + d0) * 0.5f;  cH.x = (c0 + d0 - a0 - e0) * 0.5f;
        cV.x = (e0 + d0 - a0 - c0) * 0.5f;  cD.x = (a0 - e0 - c0 + d0) * 0.5f;
        cA.y = (a1 + e1 + c1 + d1) * 0.5f;  cH.y = (c1 + d1 - a1 - e1) * 0.5f;
        cV.y = (e1 + d1 - a1 - c1) * 0.5f;  cD.y = (a1 - e1 - c1 + d1) * 0.5f;
        cA.z = (a2 + e2 + c2 + d2) * 0.5f;  cH.z = (c2 + d2 - a2 - e2) * 0.5f;
        cV.z = (e2 + d2 - a2 - c2) * 0.5f;  cD.z = (a2 - e2 - c2 + d2) * 0.5f;
        cA.w = (a3 + e3 + c3 + d3) * 0.5f;  cH.w = (c3 + d3 - a3 - e3) * 0.5f;
        cV.w = (e3 + d3 - a3 - c3) * 0.5f;  cD.w = (a3 - e3 - c3 + d3) * 0.5f;

        size_t obase = (((size_t)bc * 4) * (H2 * W2) + (size_t)h2 * W2 + col / 2) / 4;
        float4* oA = reinterpret_cast<float4*>(out) + obase;
        oA[0 * plane_f4] = cA;
        oA[1 * plane_f4] = cH;
        oA[2 * plane_f4] = cV;
        oA[3 * plane_f4] = cD;
    }
}

extern "C" void kernel_launch(void* const* d_in, const int* in_sizes, int n_in,
                              void* d_out, int out_size) {
    const float* x = (const float*)d_in[0];
    float* out = (float*)d_out;
    dwt_haar_kernel<<<BLOCKS, THREADS>>>(x, out);
}

// round 8
// speedup vs baseline: 1.1269x; 1.1269x over previous
#include <cuda_runtime.h>
#include <cuda_bf16.h>

// Haar DWT, single level. Input (16,64,256,256) fp32 -> output (16,256,128,128).
// Best shape (R1): flat grid, each thread = 4 output columns of one output row.
// 4 front-batched 128-bit loads, 4 x 128-bit evict-first stores.

static constexpr int B = 16;
static constexpr int C = 64;
static constexpr int H = 256;
static constexpr int W = 256;
static constexpr int H2 = H / 2;   // 128
static constexpr int W2 = W / 2;   // 128
static constexpr int W4 = W2 / 4;  // 32 threads per output row

__global__ __launch_bounds__(256, 8)
void dwt_haar_kernel(const float* __restrict__ x, float* __restrict__ out) {
    unsigned idx = blockIdx.x * blockDim.x + threadIdx.x;
    // idx layout: [bc][h2][w4] — consecutive threads touch consecutive memory
    unsigned w4 = idx & (W4 - 1);            // 0..31
    unsigned h2 = (idx >> 5) & (H2 - 1);     // 0..127
    unsigned bc = idx >> 12;                 // 0..B*C-1

    const float* plane = x + (size_t)bc * (H * W);
    unsigned col = w4 * 8;                   // first of 8 input columns
    const float4* r0 = reinterpret_cast<const float4*>(plane + (size_t)(2 * h2) * W + col);
    const float4* r1 = reinterpret_cast<const float4*>(plane + (size_t)(2 * h2 + 1) * W + col);

    // Front-batch 4 independent 128-bit loads
    float4 t0 = r0[0];
    float4 t1 = r0[1];
    float4 b0 = r1[0];
    float4 b1 = r1[1];

    float a0 = t0.x, e0 = t0.y, c0 = b0.x, d0 = b0.y;
    float a1 = t0.z, e1 = t0.w, c1 = b0.z, d1 = b0.w;
    float a2 = t1.x, e2 = t1.y, c2 = b1.x, d2 = b1.y;
    float a3 = t1.z, e3 = t1.w, c3 = b1.z, d3 = b1.w;

    float4 cA, cH, cV, cD;
    cA.x = (a0 + e0 + c0 + d0) * 0.5f;  cH.x = (c0 + d0 - a0 - e0) * 0.5f;
    cV.x = (e0 + d0 - a0 - c0) * 0.5f;  cD.x = (a0 - e0 - c0 + d0) * 0.5f;
    cA.y = (a1 + e1 + c1 + d1) * 0.5f;  cH.y = (c1 + d1 - a1 - e1) * 0.5f;
    cV.y = (e1 + d1 - a1 - c1) * 0.5f;  cD.y = (a1 - e1 - c1 + d1) * 0.5f;
    cA.z = (a2 + e2 + c2 + d2) * 0.5f;  cH.z = (c2 + d2 - a2 - e2) * 0.5f;
    cV.z = (e2 + d2 - a2 - c2) * 0.5f;  cD.z = (a2 - e2 - c2 + d2) * 0.5f;
    cA.w = (a3 + e3 + c3 + d3) * 0.5f;  cH.w = (c3 + d3 - a3 - e3) * 0.5f;
    cV.w = (e3 + d3 - a3 - c3) * 0.5f;  cD.w = (a3 - e3 - c3 + d3) * 0.5f;

    // Output: planes bc*4 + {0..3} of (H2, W2); evict-first stores (never re-read)
    constexpr size_t plane_f4 = (size_t)(H2 * W2) / 4;
    size_t obase = (((size_t)bc * 4) * (H2 * W2) + (size_t)h2 * W2 + col / 2) / 4;
    float4* oA = reinterpret_cast<float4*>(out) + obase;
    __stcs(oA + 0 * plane_f4, cA);
    __stcs(oA + 1 * plane_f4, cH);
    __stcs(oA + 2 * plane_f4, cV);
    __stcs(oA + 3 * plane_f4, cD);
}

extern "C" void kernel_launch(void* const* d_in, const int* in_sizes, int n_in,
                              void* d_out, int out_size) {
    const float* x = (const float*)d_in[0];
    float* out = (float*)d_out;
    int total_threads = B * C * H2 * W4;   // 4,194,304
    int threads = 256;
    int blocks = total_threads / threads;  // 16384
    dwt_haar_kernel<<<blocks, threads>>>(x, out);
}